// round 1
// baseline (speedup 1.0000x reference)
#include <cuda_runtime.h>

#define NROWS 100000
#define INDIM 256
#define HID   64
#define OUTD  64

// scratch (device globals: no allocation allowed)
__device__ __align__(16) float g_H[(size_t)NROWS * HID];
__device__ __align__(16) float g_O[(size_t)NROWS * OUTD];

// ---------------------------------------------------------------------------
// Kernel 1: H = X @ W1   (100000x256 @ 256x64)
// Block: 256 threads, grid-stride over 16-row tiles. W1 (64KB) loaded once
// per block into dynamic smem; X tile (16x256 = 16KB) per iteration.
// Thread t: col c = t&63, row-group rg = t>>6 (4 rows each).
// ---------------------------------------------------------------------------
__global__ void __launch_bounds__(256, 2) gemm1_kernel(
    const float* __restrict__ X, const float* __restrict__ W1,
    float* __restrict__ H)
{
    extern __shared__ float smem[];
    float* Ws = smem;                 // [256*64]
    float* Xs = smem + INDIM * HID;   // [16*256]

    const int tid = threadIdx.x;

    // load W1 once (vectorized)
    {
        const float4* src = reinterpret_cast<const float4*>(W1);
        float4* dst = reinterpret_cast<float4*>(Ws);
        #pragma unroll
        for (int i = tid; i < (INDIM * HID) / 4; i += 256) dst[i] = src[i];
    }

    const int c  = tid & 63;
    const int rg = tid >> 6;     // 0..3
    const int ntiles = NROWS / 16;

    for (int tile = blockIdx.x; tile < ntiles; tile += gridDim.x) {
        __syncthreads();  // Xs free to overwrite (also covers Ws on 1st iter)
        {
            const float4* src =
                reinterpret_cast<const float4*>(X + (size_t)tile * 16 * INDIM);
            float4* dst = reinterpret_cast<float4*>(Xs);
            #pragma unroll
            for (int i = tid; i < (16 * INDIM) / 4; i += 256) dst[i] = src[i];
        }
        __syncthreads();

        float acc0 = 0.f, acc1 = 0.f, acc2 = 0.f, acc3 = 0.f;
        const float* xs = Xs + rg * 4 * INDIM;

        #pragma unroll 8
        for (int k = 0; k < INDIM; k += 4) {
            const float w0 = Ws[(k + 0) * HID + c];
            const float w1 = Ws[(k + 1) * HID + c];
            const float w2 = Ws[(k + 2) * HID + c];
            const float w3 = Ws[(k + 3) * HID + c];
            const float4 x0 = *reinterpret_cast<const float4*>(xs + 0 * INDIM + k);
            const float4 x1 = *reinterpret_cast<const float4*>(xs + 1 * INDIM + k);
            const float4 x2 = *reinterpret_cast<const float4*>(xs + 2 * INDIM + k);
            const float4 x3 = *reinterpret_cast<const float4*>(xs + 3 * INDIM + k);
            acc0 += x0.x * w0 + x0.y * w1 + x0.z * w2 + x0.w * w3;
            acc1 += x1.x * w0 + x1.y * w1 + x1.z * w2 + x1.w * w3;
            acc2 += x2.x * w0 + x2.y * w1 + x2.z * w2 + x2.w * w3;
            acc3 += x3.x * w0 + x3.y * w1 + x3.z * w2 + x3.w * w3;
        }

        const int rowBase = tile * 16 + rg * 4;
        H[(size_t)(rowBase + 0) * HID + c] = acc0;
        H[(size_t)(rowBase + 1) * HID + c] = acc1;
        H[(size_t)(rowBase + 2) * HID + c] = acc2;
        H[(size_t)(rowBase + 3) * HID + c] = acc3;
    }
}

// ---------------------------------------------------------------------------
// Kernel 2 (fused): O = relu(A @ H) @ W2
// Warp per row. Lane owns output cols {2*lane, 2*lane+1}.
// ---------------------------------------------------------------------------
__global__ void __launch_bounds__(256) spmm_relu_gemm2_kernel(
    const float* __restrict__ H, const float* __restrict__ W2,
    const float* __restrict__ vals, const int* __restrict__ rowptr,
    const int* __restrict__ colind, float* __restrict__ O)
{
    __shared__ float W2s[HID * OUTD];   // 16KB
    __shared__ float Hs[8][HID];        // per-warp staging

    const int tid = threadIdx.x;
    {
        const float4* src = reinterpret_cast<const float4*>(W2);
        float4* dst = reinterpret_cast<float4*>(W2s);
        #pragma unroll
        for (int i = tid; i < (HID * OUTD) / 4; i += 256) dst[i] = src[i];
    }
    __syncthreads();

    const int warp = tid >> 5;
    const int lane = tid & 31;
    const int row  = blockIdx.x * 8 + warp;
    if (row >= NROWS) return;

    const int start = rowptr[row];
    const int end   = rowptr[row + 1];

    float ax = 0.f, ay = 0.f;
    #pragma unroll 4
    for (int e = start; e < end; ++e) {
        const int   col = colind[e];
        const float v   = vals[e];
        const float2 h  =
            *reinterpret_cast<const float2*>(H + (size_t)col * HID + 2 * lane);
        ax += v * h.x;
        ay += v * h.y;
    }
    ax = fmaxf(ax, 0.f);
    ay = fmaxf(ay, 0.f);

    Hs[warp][2 * lane]     = ax;
    Hs[warp][2 * lane + 1] = ay;
    __syncwarp();

    float ox = 0.f, oy = 0.f;
    #pragma unroll
    for (int j = 0; j < HID; ++j) {
        const float a = Hs[warp][j];
        const float2 w =
            *reinterpret_cast<const float2*>(W2s + j * OUTD + 2 * lane);
        ox += a * w.x;
        oy += a * w.y;
    }

    *reinterpret_cast<float2*>(O + (size_t)row * OUTD + 2 * lane) =
        make_float2(ox, oy);
}

// ---------------------------------------------------------------------------
// Kernel 3: out = A @ O
// ---------------------------------------------------------------------------
__global__ void __launch_bounds__(256) spmm2_kernel(
    const float* __restrict__ O, const float* __restrict__ vals,
    const int* __restrict__ rowptr, const int* __restrict__ colind,
    float* __restrict__ out)
{
    const int tid  = threadIdx.x;
    const int warp = tid >> 5;
    const int lane = tid & 31;
    const int row  = blockIdx.x * 8 + warp;
    if (row >= NROWS) return;

    const int start = rowptr[row];
    const int end   = rowptr[row + 1];

    float ax = 0.f, ay = 0.f;
    #pragma unroll 4
    for (int e = start; e < end; ++e) {
        const int   col = colind[e];
        const float v   = vals[e];
        const float2 o  =
            *reinterpret_cast<const float2*>(O + (size_t)col * OUTD + 2 * lane);
        ax += v * o.x;
        ay += v * o.y;
    }

    *reinterpret_cast<float2*>(out + (size_t)row * OUTD + 2 * lane) =
        make_float2(ax, ay);
}

// ---------------------------------------------------------------------------
extern "C" void kernel_launch(void* const* d_in, const int* in_sizes, int n_in,
                              void* d_out, int out_size)
{
    const float* X      = (const float*)d_in[0];
    const float* W1     = (const float*)d_in[1];
    const float* W2     = (const float*)d_in[2];
    const float* vals   = (const float*)d_in[3];
    const int*   rowptr = (const int*)d_in[4];
    const int*   colind = (const int*)d_in[5];
    float*       out    = (float*)d_out;

    float* H; cudaGetSymbolAddress((void**)&H, g_H);
    float* O; cudaGetSymbolAddress((void**)&O, g_O);

    const int smem1 = (INDIM * HID + 16 * INDIM) * sizeof(float);  // 80KB
    static bool attr_set = false;
    if (!attr_set) {
        cudaFuncSetAttribute(gemm1_kernel,
                             cudaFuncAttributeMaxDynamicSharedMemorySize, smem1);
        attr_set = true;
    }

    gemm1_kernel<<<304, 256, smem1>>>(X, W1, H);
    spmm_relu_gemm2_kernel<<<(NROWS + 7) / 8, 256>>>(H, W2, vals, rowptr,
                                                     colind, O);
    spmm2_kernel<<<(NROWS + 7) / 8, 256>>>(O, vals, rowptr, colind, out);
}

// round 2
// speedup vs baseline: 1.1841x; 1.1841x over previous
#include <cuda_runtime.h>

#define NROWS 100000
#define INDIM 256
#define HID   64
#define OUTD  64

// scratch (device globals: no allocation allowed)
__device__ __align__(16) float g_H[(size_t)NROWS * HID];
__device__ __align__(16) float g_O[(size_t)NROWS * OUTD];

// ---------------------------------------------------------------------------
// Kernel 1: H = X @ W1   (100000x256 @ 256x64)
// Block: 256 threads, grid-stride over 32-row tiles.
// W1 (64KB) persistent in smem; X tile (32x256 = 32KB) per iteration.
// Thread t: col-pair cp = (t&31)*2, row group rg = (t>>5)*4  (4 rows x 2 cols).
// X smem reads are warp-broadcast (all lanes in a warp share rg) -> ~free on
// the crossbar; W float2 reads are lane-consecutive -> conflict-free.
// ---------------------------------------------------------------------------
__global__ void __launch_bounds__(256, 2) gemm1_kernel(
    const float* __restrict__ X, const float* __restrict__ W1,
    float* __restrict__ H)
{
    extern __shared__ float smem[];
    float* Ws = smem;                 // [256*64]  64KB
    float* Xs = smem + INDIM * HID;   // [32*256]  32KB

    const int tid = threadIdx.x;

    // load W1 once (vectorized)
    {
        const float4* src = reinterpret_cast<const float4*>(W1);
        float4* dst = reinterpret_cast<float4*>(Ws);
        #pragma unroll
        for (int i = tid; i < (INDIM * HID) / 4; i += 256) dst[i] = src[i];
    }

    const int cp = (tid & 31) * 2;      // 0,2,..,62
    const int rg = (tid >> 5) * 4;      // 0,4,..,28
    const int ntiles = NROWS / 32;      // 3125

    for (int tile = blockIdx.x; tile < ntiles; tile += gridDim.x) {
        __syncthreads();  // Xs free to overwrite (also covers Ws on 1st iter)
        {
            const float4* src =
                reinterpret_cast<const float4*>(X + (size_t)tile * 32 * INDIM);
            float4* dst = reinterpret_cast<float4*>(Xs);
            #pragma unroll
            for (int i = tid; i < (32 * INDIM) / 4; i += 256) dst[i] = src[i];
        }
        __syncthreads();

        float a00 = 0.f, a01 = 0.f, a10 = 0.f, a11 = 0.f;
        float a20 = 0.f, a21 = 0.f, a30 = 0.f, a31 = 0.f;
        const float* xs = Xs + rg * INDIM;

        #pragma unroll 4
        for (int k = 0; k < INDIM; k += 4) {
            const float2 w0 = *reinterpret_cast<const float2*>(Ws + (k + 0) * HID + cp);
            const float2 w1 = *reinterpret_cast<const float2*>(Ws + (k + 1) * HID + cp);
            const float2 w2 = *reinterpret_cast<const float2*>(Ws + (k + 2) * HID + cp);
            const float2 w3 = *reinterpret_cast<const float2*>(Ws + (k + 3) * HID + cp);
            const float4 x0 = *reinterpret_cast<const float4*>(xs + 0 * INDIM + k);
            const float4 x1 = *reinterpret_cast<const float4*>(xs + 1 * INDIM + k);
            const float4 x2 = *reinterpret_cast<const float4*>(xs + 2 * INDIM + k);
            const float4 x3 = *reinterpret_cast<const float4*>(xs + 3 * INDIM + k);

            a00 += x0.x * w0.x + x0.y * w1.x + x0.z * w2.x + x0.w * w3.x;
            a01 += x0.x * w0.y + x0.y * w1.y + x0.z * w2.y + x0.w * w3.y;
            a10 += x1.x * w0.x + x1.y * w1.x + x1.z * w2.x + x1.w * w3.x;
            a11 += x1.x * w0.y + x1.y * w1.y + x1.z * w2.y + x1.w * w3.y;
            a20 += x2.x * w0.x + x2.y * w1.x + x2.z * w2.x + x2.w * w3.x;
            a21 += x2.x * w0.y + x2.y * w1.y + x2.z * w2.y + x2.w * w3.y;
            a30 += x3.x * w0.x + x3.y * w1.x + x3.z * w2.x + x3.w * w3.x;
            a31 += x3.x * w0.y + x3.y * w1.y + x3.z * w2.y + x3.w * w3.y;
        }

        const int rowBase = tile * 32 + rg;
        *reinterpret_cast<float2*>(H + (size_t)(rowBase + 0) * HID + cp) = make_float2(a00, a01);
        *reinterpret_cast<float2*>(H + (size_t)(rowBase + 1) * HID + cp) = make_float2(a10, a11);
        *reinterpret_cast<float2*>(H + (size_t)(rowBase + 2) * HID + cp) = make_float2(a20, a21);
        *reinterpret_cast<float2*>(H + (size_t)(rowBase + 3) * HID + cp) = make_float2(a30, a31);
    }
}

// ---------------------------------------------------------------------------
// Kernel 2 (fused): O = relu(A @ H) @ W2
// Warp per row; DEG=16 fast path fully unrolled -> 16 gathers in flight.
// ---------------------------------------------------------------------------
__global__ void __launch_bounds__(256) spmm_relu_gemm2_kernel(
    const float* __restrict__ H, const float* __restrict__ W2,
    const float* __restrict__ vals, const int* __restrict__ rowptr,
    const int* __restrict__ colind, float* __restrict__ O)
{
    __shared__ float W2s[HID * OUTD];   // 16KB
    __shared__ float Hs[8][HID];        // per-warp staging

    const int tid = threadIdx.x;
    {
        const float4* src = reinterpret_cast<const float4*>(W2);
        float4* dst = reinterpret_cast<float4*>(W2s);
        #pragma unroll
        for (int i = tid; i < (HID * OUTD) / 4; i += 256) dst[i] = src[i];
    }
    __syncthreads();

    const int warp = tid >> 5;
    const int lane = tid & 31;
    const int row  = blockIdx.x * 8 + warp;
    if (row >= NROWS) return;

    const int start = rowptr[row];
    const int deg   = rowptr[row + 1] - start;

    float ax = 0.f, ay = 0.f;
    if (deg == 16) {
        #pragma unroll
        for (int e = 0; e < 16; ++e) {
            const int   col = __ldg(colind + start + e);
            const float v   = __ldg(vals + start + e);
            const float2 h  =
                *reinterpret_cast<const float2*>(H + (size_t)col * HID + 2 * lane);
            ax += v * h.x;
            ay += v * h.y;
        }
    } else {
        for (int e = start; e < start + deg; ++e) {
            const int   col = colind[e];
            const float v   = vals[e];
            const float2 h  =
                *reinterpret_cast<const float2*>(H + (size_t)col * HID + 2 * lane);
            ax += v * h.x;
            ay += v * h.y;
        }
    }
    ax = fmaxf(ax, 0.f);
    ay = fmaxf(ay, 0.f);

    Hs[warp][2 * lane]     = ax;
    Hs[warp][2 * lane + 1] = ay;
    __syncwarp();

    float ox = 0.f, oy = 0.f;
    #pragma unroll
    for (int j = 0; j < HID; ++j) {
        const float a = Hs[warp][j];
        const float2 w =
            *reinterpret_cast<const float2*>(W2s + j * OUTD + 2 * lane);
        ox += a * w.x;
        oy += a * w.y;
    }

    *reinterpret_cast<float2*>(O + (size_t)row * OUTD + 2 * lane) =
        make_float2(ox, oy);
}

// ---------------------------------------------------------------------------
// Kernel 3: out = A @ O
// ---------------------------------------------------------------------------
__global__ void __launch_bounds__(256) spmm2_kernel(
    const float* __restrict__ O, const float* __restrict__ vals,
    const int* __restrict__ rowptr, const int* __restrict__ colind,
    float* __restrict__ out)
{
    const int tid  = threadIdx.x;
    const int warp = tid >> 5;
    const int lane = tid & 31;
    const int row  = blockIdx.x * 8 + warp;
    if (row >= NROWS) return;

    const int start = rowptr[row];
    const int deg   = rowptr[row + 1] - start;

    float ax = 0.f, ay = 0.f;
    if (deg == 16) {
        #pragma unroll
        for (int e = 0; e < 16; ++e) {
            const int   col = __ldg(colind + start + e);
            const float v   = __ldg(vals + start + e);
            const float2 o  =
                *reinterpret_cast<const float2*>(O + (size_t)col * OUTD + 2 * lane);
            ax += v * o.x;
            ay += v * o.y;
        }
    } else {
        for (int e = start; e < start + deg; ++e) {
            const int   col = colind[e];
            const float v   = vals[e];
            const float2 o  =
                *reinterpret_cast<const float2*>(O + (size_t)col * OUTD + 2 * lane);
            ax += v * o.x;
            ay += v * o.y;
        }
    }

    *reinterpret_cast<float2*>(out + (size_t)row * OUTD + 2 * lane) =
        make_float2(ax, ay);
}

// ---------------------------------------------------------------------------
extern "C" void kernel_launch(void* const* d_in, const int* in_sizes, int n_in,
                              void* d_out, int out_size)
{
    const float* X      = (const float*)d_in[0];
    const float* W1     = (const float*)d_in[1];
    const float* W2     = (const float*)d_in[2];
    const float* vals   = (const float*)d_in[3];
    const int*   rowptr = (const int*)d_in[4];
    const int*   colind = (const int*)d_in[5];
    float*       out    = (float*)d_out;

    float* H; cudaGetSymbolAddress((void**)&H, g_H);
    float* O; cudaGetSymbolAddress((void**)&O, g_O);

    const int smem1 = (INDIM * HID + 32 * INDIM) * sizeof(float);  // 96KB
    static bool attr_set = false;
    if (!attr_set) {
        cudaFuncSetAttribute(gemm1_kernel,
                             cudaFuncAttributeMaxDynamicSharedMemorySize, smem1);
        attr_set = true;
    }

    gemm1_kernel<<<296, 256, smem1>>>(X, W1, H);
    spmm_relu_gemm2_kernel<<<(NROWS + 7) / 8, 256>>>(H, W2, vals, rowptr,
                                                     colind, O);
    spmm2_kernel<<<(NROWS + 7) / 8, 256>>>(O, vals, rowptr, colind, out);
}